// round 14
// baseline (speedup 1.0000x reference)
#include <cuda_runtime.h>
#include <math.h>

#define T_STEPS 512
#define BATCH   512
#define IN_DIM  4
#define AUX_DIM 28
#define OUT_DIM 32
#define G_DIM   64
#define NROWS   1184      // 128 (W_i) + 1024 (W_r) + 32 (W_o)
#define NCTA    64
#define BS      8         // batch rows per CTA
#define NTHREADS 640
#define NGEMM   (NROWS / 2)   // 592 GEMM threads, 2 rows each
#define R_SM    636           // rows resident in smem (tid < 318)

typedef unsigned long long ull;

// ---------------- device globals ----------------
__device__ float g_WcatT[G_DIM * NROWS];   // [g][row]
__device__ float g_bcat[NROWS];
__device__ float g_E[OUT_DIM * G_DIM];     // exp(W_s)        [o][g]
__device__ float g_sWr[G_DIM * OUT_DIM];   // sigmoid(W_rm.T) [g][o]
__device__ float g_d0[G_DIM];              // b0 @ exp(W_s)   [g]
__device__ ull   g_msg[2][NCTA * BS];      // (tag<<32)|float partial, 8 per CTA

__device__ __forceinline__ float sigm(float x) {
    return __fdividef(1.0f, 1.0f + __expf(-x));
}
__device__ __forceinline__ float tanh_fast(float x) {
    x = fminf(fmaxf(x, -12.0f), 12.0f);
    float e = __expf(2.0f * x);
    return __fdividef(e - 1.0f, e + 1.0f);
}
__device__ __forceinline__ float wsum32(float v) {
#pragma unroll
    for (int s = 16; s > 0; s >>= 1) v += __shfl_xor_sync(0xffffffffu, v, s);
    return v;
}
__device__ __forceinline__ void ffma2(ull& d, ull a, ull b) {
    asm("fma.rn.f32x2 %0, %1, %2, %0;" : "+l"(d) : "l"(a), "l"(b));
}
__device__ __forceinline__ ull dup2(float x) {
    ull r; asm("mov.b64 %0, {%1, %1};" : "=l"(r) : "f"(x)); return r;
}
__device__ __forceinline__ float2 unp(ull v) {
    float2 r;
    r.x = __uint_as_float((unsigned)v);
    r.y = __uint_as_float((unsigned)(v >> 32));
    return r;
}
__device__ __forceinline__ void ld_vol_v2u64(const ull* p, ull& a, ull& b) {
    asm volatile("ld.volatile.global.v2.u64 {%0, %1}, [%2];"
                 : "=l"(a), "=l"(b) : "l"(p) : "memory");
}

// one g-iter: 8 batches (4 pairs in F0,F1) vs 2-row weight W -> 8 accs
// ACC[0..3] = row r0 pairs 0..3 ; ACC[4..7] = row r0+1 pairs 0..3
#define GEMM_STEP8(ACC, F0, F1, W) do {                  \
    float2 _wf = unp(W);                                 \
    ull _w0 = dup2(_wf.x), _w1 = dup2(_wf.y);            \
    ffma2(ACC[0], F0.x, _w0); ffma2(ACC[1], F0.y, _w0);  \
    ffma2(ACC[2], F1.x, _w0); ffma2(ACC[3], F1.y, _w0);  \
    ffma2(ACC[4], F0.x, _w1); ffma2(ACC[5], F0.y, _w1);  \
    ffma2(ACC[6], F1.x, _w1); ffma2(ACC[7], F1.y, _w1);  \
} while (0)

// ---------------- prep ----------------
__global__ void prep_kernel(const float* __restrict__ W_i, const float* __restrict__ b_i,
                            const float* __restrict__ W_r, const float* __restrict__ b_r,
                            const float* __restrict__ W_o, const float* __restrict__ b_o,
                            const float* __restrict__ W_s, const float* __restrict__ W_rm,
                            const float* __restrict__ b0)
{
    int idx = blockIdx.x * blockDim.x + threadIdx.x;
    if (idx < G_DIM * NROWS) {
        int g = idx / NROWS, r = idx % NROWS;
        float v;
        if (r < 128)        v = W_i[r * G_DIM + g];
        else if (r < 1152)  v = W_r[(r - 128) * G_DIM + g];
        else                v = W_o[(r - 1152) * G_DIM + g];
        g_WcatT[idx] = v;
    }
    int i2 = idx - G_DIM * NROWS;
    if (i2 >= 0 && i2 < NROWS)
        g_bcat[i2] = (i2 < 128) ? b_i[i2] : (i2 < 1152) ? b_r[i2 - 128] : b_o[i2 - 1152];
    int i3 = i2 - NROWS;
    if (i3 >= 0 && i3 < OUT_DIM * G_DIM) g_E[i3] = expf(W_s[i3]);
    int i4 = i3 - OUT_DIM * G_DIM;
    if (i4 >= 0 && i4 < G_DIM * OUT_DIM) {
        int g = i4 / OUT_DIM, o = i4 % OUT_DIM;
        g_sWr[i4] = 1.0f / (1.0f + expf(-W_rm[o * G_DIM + g]));
    }
    int i5 = i4 - G_DIM * OUT_DIM;
    if (i5 >= 0 && i5 < G_DIM) {
        float a = 0.0f;
        for (int o = 0; o < OUT_DIM; ++o) a += b0[o] * expf(W_s[o * G_DIM + i5]);
        g_d0[i5] = a;
    }
    int i6 = i5 - G_DIM;
    if (i6 >= 0 && i6 < 2 * NCTA * BS) ((ull*)g_msg)[i6] = 0ull;
}

// ---------------- smem layout (float offsets) ----------------
#define OFF_WS    0                        // [64][R_SM] = 40704
#define OFF_E     (OFF_WS + 64 * R_SM)     // 40704
#define OFF_SWR   (OFF_E + 2048)           // 42752
#define OFF_BC    (OFF_SWR + 2048)         // 44800
#define OFF_F1S   (OFF_BC + 1184)          // 45984: [2][32][8] dbl-buffered x feat
#define OFF_CFS   (OFF_F1S + 512)          // 46496: [32][8] raw carry, g-major
#define OFF_CNS   (OFF_CFS + 256)          // 46752: [32][8] normalized carry
#define OFF_GI    (OFF_CNS + 256)          // 47008: [8][128]
#define OFF_RR    (OFF_GI + 1024)          // 48032: [8][1024]
#define OFF_OS    (OFF_RR + 8192)          // 56224: [8][32]
#define OFF_C     (OFF_OS + 256)           // 56480: [8][32]
#define OFF_XM    (OFF_C + 256)            // 56736: [2][8][4]
#define OFF_CR    (OFF_XM + 64)            // 56800: [8][32]
#define OFF_CI    (OFF_CR + 256)           // 57056: [8][4]
#define OFF_TH    (OFF_CI + 32)            // 57088: [8][64]
#define OFF_D0    (OFF_TH + 512)           // 57600: [64]
#define OFF_OV1   (OFF_D0 + 64)            // 57664: [8][32]
#define OFF_LNG   (OFF_OV1 + 256)          // 57920
#define OFF_LNB   (OFF_LNG + 32)           // 57952
#define OFF_MISC  (OFF_LNB + 32)           // 57984: [8]; [4]=S
#define SMEM_FLOATS (OFF_MISC + 8)         // 57992
#define SMEM_BYTES  (SMEM_FLOATS * 4)      // 231968 B

__global__ void __launch_bounds__(NTHREADS, 1)
mclstm_kernel(const float* __restrict__ xm, const float* __restrict__ xa,
              const float* __restrict__ ln_g, const float* __restrict__ ln_b,
              float* __restrict__ out)
{
    extern __shared__ float sm[];
    float* Ws     = sm + OFF_WS;
    float* E_s    = sm + OFF_E;
    float* sWr_s  = sm + OFF_SWR;
    float* bc_s   = sm + OFF_BC;
    float* f1s2   = sm + OFF_F1S;   // [2][256]
    float* cfs    = sm + OFF_CFS;
    float* cns    = sm + OFF_CNS;
    float* gi_s   = sm + OFF_GI;
    float* rr_s   = sm + OFF_RR;
    float* o_s    = sm + OFF_OS;
    float* c_s    = sm + OFF_C;
    float* xm2    = sm + OFF_XM;    // [2][32]
    float* coef_r = sm + OFF_CR;
    float* coef_i = sm + OFF_CI;
    float* th_s   = sm + OFF_TH;
    float* d0_s   = sm + OFF_D0;
    float* ov1_s  = sm + OFF_OV1;
    float* lng_s  = sm + OFF_LNG;
    float* lnb_s  = sm + OFF_LNB;
    float* misc   = sm + OFF_MISC;

    const int tid = threadIdx.x;
    const int cta = blockIdx.x;
    const int bbase = cta * BS;
    const size_t OSTRIDE = (size_t)T_STEPS * BATCH * OUT_DIM;
    const int r0 = tid * 2;

    // feeders: tid 512..639, two (pb, pg) slots each (256 slots total)
    const bool feeder = (tid >= 512);
    int pb0 = 0, pg0 = 0, pb1 = 0, pg1 = 0;
    float xn0 = 0.0f, xn1 = 0.0f;
    if (feeder) {
        int idx = tid - 512;
        pb0 = idx >> 5; pg0 = idx & 31;
        pb1 = pb0 + 4;  pg1 = pg0;
    }

    // ---- one-time smem fills ----
    for (int i = tid; i < 64 * R_SM; i += NTHREADS) {
        int g = i / R_SM, r = i - g * R_SM;
        Ws[i] = g_WcatT[g * NROWS + r];
    }
    for (int i = tid; i < 2048; i += NTHREADS) { E_s[i] = g_E[i]; sWr_s[i] = g_sWr[i]; }
    for (int i = tid; i < NROWS; i += NTHREADS) bc_s[i] = g_bcat[i];
    if (tid < G_DIM) d0_s[tid] = g_d0[tid];
    if (tid < OUT_DIM) { lng_s[tid] = ln_g[tid]; lnb_s[tid] = ln_b[tid]; }
    if (tid < 256) { c_s[tid] = 0.0f; cfs[tid] = 0.0f; cns[tid] = 0.0f; }
    if (tid < 8) misc[tid] = 0.0f;
    if (feeder) {
        // x(0) into buffer 0
        float a0 = (pg0 < IN_DIM) ? xm[(size_t)(bbase + pb0) * IN_DIM + pg0]
                                  : xa[(size_t)(bbase + pb0) * AUX_DIM + (pg0 - IN_DIM)];
        float a1 = (pg1 < IN_DIM) ? xm[(size_t)(bbase + pb1) * IN_DIM + pg1]
                                  : xa[(size_t)(bbase + pb1) * AUX_DIM + (pg1 - IN_DIM)];
        f1s2[pg0 * 8 + pb0] = a0;
        f1s2[pg1 * 8 + pb1] = a1;
        if (pg0 < IN_DIM) { xm2[pb0 * 4 + pg0] = a0; xm2[pb1 * 4 + pg1] = a1; }
        // x(1) into registers
        xn0 = (pg0 < IN_DIM) ? xm[((size_t)BATCH + bbase + pb0) * IN_DIM + pg0]
                             : xa[((size_t)BATCH + bbase + pb0) * AUX_DIM + (pg0 - IN_DIM)];
        xn1 = (pg1 < IN_DIM) ? xm[((size_t)BATCH + bbase + pb1) * IN_DIM + pg1]
                             : xa[((size_t)BATCH + bbase + pb1) * AUX_DIM + (pg1 - IN_DIM)];
    }

    for (int t = 0; t < T_STEPS; ++t) {
        __syncthreads();   // sync A: carry state (cfs, c_s) + feat buffer t&1 ready

        const int bufn = (t + 1) & 1;
        // ---- feeders: commit x(t+1), prefetch x(t+2) ----
        if (feeder) {
            f1s2[bufn * 256 + pg0 * 8 + pb0] = xn0;
            f1s2[bufn * 256 + pg1 * 8 + pb1] = xn1;
            if (pg0 < IN_DIM) { xm2[bufn * 32 + pb0 * 4 + pg0] = xn0; xm2[bufn * 32 + pb1 * 4 + pg1] = xn1; }
            if (t + 2 < T_STEPS) {
                xn0 = (pg0 < IN_DIM)
                    ? xm[((size_t)(t + 2) * BATCH + bbase + pb0) * IN_DIM + pg0]
                    : xa[((size_t)(t + 2) * BATCH + bbase + pb0) * AUX_DIM + (pg0 - IN_DIM)];
                xn1 = (pg1 < IN_DIM)
                    ? xm[((size_t)(t + 2) * BATCH + bbase + pb1) * IN_DIM + pg1]
                    : xa[((size_t)(t + 2) * BATCH + bbase + pb1) * AUX_DIM + (pg1 - IN_DIM)];
            }
        }
        // ---- poller warp 19: gather 512 partials -> S, write cns = cfs * invS ----
        if (t > 0 && tid >= 608) {
            const int lane = tid - 608;
            const unsigned tg = (unsigned)t;
            const ull* base = &g_msg[t & 1][lane * 16];
            float p;
            for (;;) {
                ull v[16];
#pragma unroll
                for (int k = 0; k < 8; ++k) ld_vol_v2u64(base + 2 * k, v[2 * k], v[2 * k + 1]);
                unsigned bad = 0;
#pragma unroll
                for (int k = 0; k < 16; ++k) bad |= ((unsigned)(v[k] >> 32)) ^ tg;
                if (bad == 0) {
                    float s0 = 0.f, s1 = 0.f;
#pragma unroll
                    for (int k = 0; k < 16; k += 2) {
                        s0 += __uint_as_float((unsigned)v[k]);
                        s1 += __uint_as_float((unsigned)v[k + 1]);
                    }
                    p = s0 + s1;
                    break;
                }
            }
            p = wsum32(p);
            float inv = __fdividef(1.0f, p + 1e-5f);
            if (lane == 0) misc[4] = p;
            float4 c0 = *(const float4*)(cfs + lane * 8);
            float4 c1 = *(const float4*)(cfs + lane * 8 + 4);
            c0.x *= inv; c0.y *= inv; c0.z *= inv; c0.w *= inv;
            c1.x *= inv; c1.y *= inv; c1.z *= inv; c1.w *= inv;
            *(float4*)(cns + lane * 8)     = c0;
            *(float4*)(cns + lane * 8 + 4) = c1;
        }

        // ---- x-half GEMM (g = 0..31), 8 batches, accs reused for c-half ----
        ull acc[8];
        if (tid < NGEMM) {
#pragma unroll
            for (int k = 0; k < 8; ++k) acc[k] = 0ull;
            const ulonglong2* fU = (const ulonglong2*)(f1s2 + (t & 1) * 256);
            if (tid < R_SM / 2) {
#pragma unroll 4
                for (int g = 0; g < 32; ++g) {
                    ulonglong2 f0 = fU[g * 2], f1 = fU[g * 2 + 1];
                    ull w = *(const ull*)(Ws + g * R_SM + r0);
                    GEMM_STEP8(acc, f0, f1, w);
                }
            } else {
#pragma unroll 4
                for (int g = 0; g < 32; ++g) {
                    ulonglong2 f0 = fU[g * 2], f1 = fU[g * 2 + 1];
                    ull w = __ldg((const ull*)(g_WcatT + g * NROWS + r0));
                    GEMM_STEP8(acc, f0, f1, w);
                }
            }
        }
        __syncthreads();   // sync B: cns + misc[4] ready
        const float invS = __fdividef(1.0f, misc[4] + 1e-5f);

        // ---- c-half GEMM (g = 32..63) on normalized carry ----
        if (tid < NGEMM) {
            const ulonglong2* cU = (const ulonglong2*)cns;
            if (tid < R_SM / 2) {
#pragma unroll 4
                for (int g = 0; g < 32; ++g) {
                    ulonglong2 c0 = cU[g * 2], c1 = cU[g * 2 + 1];
                    ull w = *(const ull*)(Ws + (32 + g) * R_SM + r0);
                    GEMM_STEP8(acc, c0, c1, w);
                }
            } else {
#pragma unroll 4
                for (int g = 0; g < 32; ++g) {
                    ulonglong2 c0 = cU[g * 2], c1 = cU[g * 2 + 1];
                    ull w = __ldg((const ull*)(g_WcatT + (32 + g) * NROWS + r0));
                    GEMM_STEP8(acc, c0, c1, w);
                }
            }
        }

        // ---- combine: bias + activation + row-sum partials ----
        float s[8];
        if (tid < NGEMM) {
            float2 bb = *(const float2*)&bc_s[r0];
            if (r0 < 128) {
#pragma unroll
                for (int pr = 0; pr < 4; ++pr) {
                    float2 rv0 = unp(acc[pr]), rv1 = unp(acc[4 + pr]);
                    float v00 = sigm(rv0.x + bb.x), v01 = sigm(rv1.x + bb.y);
                    float v10 = sigm(rv0.y + bb.x), v11 = sigm(rv1.y + bb.y);
                    *(float2*)&gi_s[(2 * pr) * 128 + r0]     = make_float2(v00, v01);
                    *(float2*)&gi_s[(2 * pr + 1) * 128 + r0] = make_float2(v10, v11);
                    s[2 * pr] = v00 + v01; s[2 * pr + 1] = v10 + v11;
                }
            } else if (r0 < 1152) {
#pragma unroll
                for (int pr = 0; pr < 4; ++pr) {
                    float2 rv0 = unp(acc[pr]), rv1 = unp(acc[4 + pr]);
                    float v00 = fmaxf(rv0.x + bb.x, 0.0f), v01 = fmaxf(rv1.x + bb.y, 0.0f);
                    float v10 = fmaxf(rv0.y + bb.x, 0.0f), v11 = fmaxf(rv1.y + bb.y, 0.0f);
                    *(float2*)&rr_s[(2 * pr) * 1024 + (r0 - 128)]     = make_float2(v00, v01);
                    *(float2*)&rr_s[(2 * pr + 1) * 1024 + (r0 - 128)] = make_float2(v10, v11);
                    s[2 * pr] = v00 + v01; s[2 * pr + 1] = v10 + v11;
                }
            } else {
#pragma unroll
                for (int pr = 0; pr < 4; ++pr) {
                    float2 rv0 = unp(acc[pr]), rv1 = unp(acc[4 + pr]);
                    *(float2*)&o_s[(2 * pr) * 32 + (r0 - 1152)] =
                        make_float2(sigm(rv0.x + bb.x), sigm(rv1.x + bb.y));
                    *(float2*)&o_s[(2 * pr + 1) * 32 + (r0 - 1152)] =
                        make_float2(sigm(rv0.y + bb.x), sigm(rv1.y + bb.y));
                }
            }
        }
        // ---- th = tanh(invS*(c@E) - d0), 512 threads, shuffle-broadcast c ----
        if (tid < 512) {
            int b = tid >> 6, g = tid & 63;
            float cv = c_s[b * 32 + (tid & 31)];
            float q0 = 0.f, q1 = 0.f;
#pragma unroll
            for (int o = 0; o < 32; o += 2) {
                float c0 = __shfl_sync(0xffffffffu, cv, o);
                float c1 = __shfl_sync(0xffffffffu, cv, o + 1);
                q0 = fmaf(c0, E_s[o * 64 + g],       q0);
                q1 = fmaf(c1, E_s[(o + 1) * 64 + g], q1);
            }
            th_s[tid] = tanh_fast(fmaf(invS, q0 + q1, -d0_s[g]));
        }
        // ---- 16-lane reductions for coef denominators (warps 0-17) ----
        if (tid < 576) {
#pragma unroll
            for (int sh = 1; sh <= 8; sh <<= 1) {
#pragma unroll
                for (int b = 0; b < 8; ++b)
                    s[b] += __shfl_xor_sync(0xffffffffu, s[b], sh);
            }
            if ((tid & 15) == 0) {
                if (tid < 64) {
                    int ii = tid >> 4;
                    const float* xmb = xm2 + (t & 1) * 32;
#pragma unroll
                    for (int b = 0; b < 8; ++b)
                        coef_i[b * 4 + ii] = __fdividef(xmb[b * 4 + ii], fmaxf(s[b], 1e-12f));
                } else {
                    int n = (tid - 64) >> 4;
#pragma unroll
                    for (int b = 0; b < 8; ++b)
                        coef_r[b * 32 + n] = __fdividef(c_s[b * 32 + n], fmaxf(s[b], 1e-12f));
                }
            }
        }
        __syncthreads();   // sync C

        // ---- epilogue: m matvec (warps 0-7) | LayerNorm (warps 12-19) ----
        if (tid < 256) {
            int b = tid >> 5, o = tid & 31;
            float m0, m1, m2 = 0.f, m3 = 0.f;
            m0 = coef_i[b * 4 + 0] * gi_s[b * 128 + o]
               + coef_i[b * 4 + 1] * gi_s[b * 128 + 32 + o];
            m1 = coef_i[b * 4 + 2] * gi_s[b * 128 + 64 + o]
               + coef_i[b * 4 + 3] * gi_s[b * 128 + 96 + o];
#pragma unroll
            for (int n = 0; n < 32; n += 4) {
                m0 = fmaf(coef_r[b * 32 + n],     rr_s[b * 1024 + n * 32 + o],       m0);
                m1 = fmaf(coef_r[b * 32 + n + 1], rr_s[b * 1024 + (n + 1) * 32 + o], m1);
                m2 = fmaf(coef_r[b * 32 + n + 2], rr_s[b * 1024 + (n + 2) * 32 + o], m2);
                m3 = fmaf(coef_r[b * 32 + n + 3], rr_s[b * 1024 + (n + 3) * 32 + o], m3);
            }
            float m = (m0 + m1) + (m2 + m3);

            asm volatile("bar.sync 1, 512;" ::: "memory");   // join LN warps

            float og  = o_s[b * 32 + o];
            float ov1 = ov1_s[b * 32 + o];
            float f = 1.0f - og;
            float ov2 = ov1 - fmaxf(ov1 - f, 0.0f);
            float MR = fmaxf(ov2 + 1.0f - f, 0.0f) + f - 1.0f;
            float opr = og + MR;
            float h = og * m;
            float cnew = (1.0f - opr) * m;
            float mrf = MR * m;

            // publish this warp's |c| row partial immediately
            float a = wsum32(fabsf(cnew));
            if (o == 0) {
                ull msg = ((ull)(unsigned)(t + 1) << 32) | (ull)__float_as_uint(a);
                *((volatile ull*)&g_msg[(t + 1) & 1][cta * BS + b]) = msg;
            }

            size_t base = ((size_t)t * BATCH + (bbase + b)) * OUT_DIM + o;
            out[base]               = h;
            out[OSTRIDE + base]     = cnew;
            out[2 * OSTRIDE + base] = og;
            out[3 * OSTRIDE + base] = MR;
            out[4 * OSTRIDE + base] = opr;
            out[5 * OSTRIDE + base] = mrf;
            out[6 * OSTRIDE + base] = h;

            c_s[b * 32 + o] = cnew;
            cfs[o * 8 + b]  = cnew;
        } else if (tid >= 384) {
            int idx = tid - 384, b = idx >> 5, o = idx & 31;
            const float* thb = th_s + b * 64;
            float p0 = 0.f, p1 = 0.f, p2 = 0.f, p3 = 0.f;
#pragma unroll
            for (int g = 0; g < 64; g += 4) {
                p0 = fmaf(thb[g],     sWr_s[g * 32 + o],       p0);
                p1 = fmaf(thb[g + 1], sWr_s[(g + 1) * 32 + o], p1);
                p2 = fmaf(thb[g + 2], sWr_s[(g + 2) * 32 + o], p2);
                p3 = fmaf(thb[g + 3], sWr_s[(g + 3) * 32 + o], p3);
            }
            float pre = (p0 + p1) + (p2 + p3);
            float s1v = pre, s2v = pre * pre;
#pragma unroll
            for (int sft = 16; sft > 0; sft >>= 1) {
                s1v += __shfl_xor_sync(0xffffffffu, s1v, sft);
                s2v += __shfl_xor_sync(0xffffffffu, s2v, sft);
            }
            float mu  = s1v * (1.0f / 32.0f);
            float var = fmaxf(s2v * (1.0f / 32.0f) - mu * mu, 0.0f);
            ov1_s[idx] = (pre - mu) * rsqrtf(var + 1e-5f) * lng_s[o] + lnb_s[o];

            asm volatile("bar.sync 1, 512;" ::: "memory");   // release m warps
        }
    }
}

// ---------------- launch ----------------
extern "C" void kernel_launch(void* const* d_in, const int* in_sizes, int n_in,
                              void* d_out, int out_size)
{
    const float* xm   = (const float*)d_in[0];
    const float* xa   = (const float*)d_in[1];
    const float* W_i  = (const float*)d_in[2];
    const float* b_i  = (const float*)d_in[3];
    const float* W_r  = (const float*)d_in[4];
    const float* b_r  = (const float*)d_in[5];
    const float* W_o  = (const float*)d_in[6];
    const float* b_o  = (const float*)d_in[7];
    const float* W_s  = (const float*)d_in[8];
    const float* W_rm = (const float*)d_in[9];
    const float* b0   = (const float*)d_in[10];
    const float* lng  = (const float*)d_in[11];
    const float* lnb  = (const float*)d_in[12];
    float* out = (float*)d_out;

    cudaFuncSetAttribute(mclstm_kernel, cudaFuncAttributeMaxDynamicSharedMemorySize, SMEM_BYTES);

    prep_kernel<<<336, 256>>>(W_i, b_i, W_r, b_r, W_o, b_o, W_s, W_rm, b0);
    mclstm_kernel<<<NCTA, NTHREADS, SMEM_BYTES>>>(xm, xa, lng, lnb, out);
}